// round 17
// baseline (speedup 1.0000x reference)
#include <cuda_runtime.h>
#include <math.h>
#include <stdint.h>

#define HEADS 8
#define AGENTS 49
#define WIN 32
#define BATCH 32
#define NTOK 1024
#define CH 256
#define HD 32
#define SCALE 0.17677669529663687f  // 32^-0.5

// ---------------- scratch (device globals; no runtime allocation) -----------
__device__ float g_q[BATCH*HEADS*NTOK*HD];    // (b,h,i,d)
__device__ float g_k[BATCH*HEADS*NTOK*HD];
__device__ float g_v[BATCH*HEADS*NTOK*HD];
__device__ float g_ah[BATCH*HEADS*AGENTS*HD]; // agent tokens, head layout
__device__ float g_pb[HEADS*AGENTS*NTOK];     // agent-attn position bias [h][a][i]
__device__ float g_ab[HEADS*AGENTS*NTOK];     // q-attn position bias, TRANSPOSED [h][a][i]
__device__ float g_avp[2][BATCH*HEADS*AGENTS*HD]; // agent_v UNNORMALIZED partials
__device__ float g_lp[2][BATCH*HEADS*AGENTS];     // softmax-l partials
__device__ float g_attn[BATCH*NTOK*CH];       // attention out + dwc (b,i,c)

__constant__ int c_starts[7] = {0,4,9,13,18,22,27};
__constant__ int c_ends[7]   = {5,10,14,19,23,28,32};

// ---------------- MUFU-free exp (FMA/ALU only); rel err ~3e-6 ----------------
__device__ __forceinline__ float exp_fast(float x) {
    x = fmaxf(x, -80.f);
    float y = x * 1.4426950408889634f;
    float r = y + 12582912.f;
    float t = r - 12582912.f;
    float f = y - t;
    int   n = __float_as_int(r);
    float p = 1.3333558146428443e-3f;
    p = fmaf(p, f, 9.6181291976746437e-3f);
    p = fmaf(p, f, 5.5504108664821580e-2f);
    p = fmaf(p, f, 2.4022650695910072e-1f);
    p = fmaf(p, f, 6.9314718055994531e-1f);
    p = fmaf(p, f, 1.0f);
    int e = (n - 1262485504 + 127) << 23;
    return p * __int_as_float(e);
}

// ---------------- tf32 helpers ----------------------------------------------
__device__ __forceinline__ uint32_t f2tf32(float f) {
    uint32_t r;
    asm("cvt.rna.tf32.f32 %0, %1;" : "=r"(r) : "f"(f));
    return r;
}
__device__ __forceinline__ float tf32r(float f) {
    return __uint_as_float(f2tf32(f));
}

__device__ __forceinline__ void mma_tf32(float* c, const uint32_t* a, const uint32_t* b) {
    asm volatile(
        "mma.sync.aligned.m16n8k8.row.col.f32.tf32.tf32.f32 "
        "{%0,%1,%2,%3},{%4,%5,%6,%7},{%8,%9},{%0,%1,%2,%3};"
        : "+f"(c[0]), "+f"(c[1]), "+f"(c[2]), "+f"(c[3])
        : "r"(a[0]), "r"(a[1]), "r"(a[2]), "r"(a[3]), "r"(b[0]), "r"(b[1]));
}

// ---------------- tensor-core GEMM (tf32), BM=128 BN=128 BK=32, 256 thr ------
template<bool QKV>
__global__ __launch_bounds__(256) void gemm_tc(const float* __restrict__ x,
                                               const float* __restrict__ w,
                                               const float* __restrict__ bias,
                                               float* __restrict__ out) {
    __shared__ __align__(16) uint32_t As[128 * 36];
    __shared__ __align__(16) uint32_t Bs[128 * 36];
    const int tid = threadIdx.x;
    const int bm = blockIdx.y, bn = blockIdx.x;
    const int warp = tid >> 5, lane = tid & 31;
    const int g = lane >> 2, t = lane & 3;
    const int wm = warp >> 2, wn = warp & 3;
    const int M = QKV ? (BATCH * NTOK) : (BATCH * 1025);

    const float* aptr[4];
    const float* bptr[4];
    int soff[4];
    #pragma unroll
    for (int i = 0; i < 4; i++) {
        int j = tid + i * 256;
        int row = j >> 3;
        int col4 = (j & 7) << 2;
        soff[i] = row * 36 + col4;
        int gm = bm * 128 + row;
        if (QKV) {
            int b_ = gm >> 10, ii = gm & 1023;
            aptr[i] = x + (size_t)(b_ * 1025 + 1 + ii) * 256 + col4;
        } else {
            if (gm < M) {
                int b_ = gm / 1025, tt = gm % 1025;
                aptr[i] = (tt == 0) ? (x + (size_t)b_ * 1025 * 256 + col4)
                                    : (g_attn + (size_t)(b_ * 1024 + tt - 1) * 256 + col4);
            } else {
                aptr[i] = x + col4;
            }
        }
        bptr[i] = w + (size_t)(bn * 128 + row) * 256 + col4;
    }

    float acc[4][4][4] = {};

    for (int kc = 0; kc < 256; kc += 32) {
        #pragma unroll
        for (int i = 0; i < 4; i++) {
            float4 av = *(const float4*)(aptr[i] + kc);
            float4 bv = *(const float4*)(bptr[i] + kc);
            uint4 au = make_uint4(f2tf32(av.x), f2tf32(av.y), f2tf32(av.z), f2tf32(av.w));
            uint4 bu = make_uint4(f2tf32(bv.x), f2tf32(bv.y), f2tf32(bv.z), f2tf32(bv.w));
            *(uint4*)&As[soff[i]] = au;
            *(uint4*)&Bs[soff[i]] = bu;
        }
        __syncthreads();
        #pragma unroll
        for (int ks = 0; ks < 4; ks++) {
            const int kb = ks * 8;
            uint32_t af[4][4];
            #pragma unroll
            for (int mt = 0; mt < 4; mt++) {
                int mrow = wm * 64 + mt * 16 + g;
                af[mt][0] = As[mrow * 36 + kb + t];
                af[mt][1] = As[(mrow + 8) * 36 + kb + t];
                af[mt][2] = As[mrow * 36 + kb + t + 4];
                af[mt][3] = As[(mrow + 8) * 36 + kb + t + 4];
            }
            uint32_t bf[4][2];
            #pragma unroll
            for (int nt = 0; nt < 4; nt++) {
                int nrow = wn * 32 + nt * 8 + g;
                bf[nt][0] = Bs[nrow * 36 + kb + t];
                bf[nt][1] = Bs[nrow * 36 + kb + t + 4];
            }
            #pragma unroll
            for (int mt = 0; mt < 4; mt++)
                #pragma unroll
                for (int nt = 0; nt < 4; nt++)
                    mma_tf32(acc[mt][nt], af[mt], bf[nt]);
        }
        __syncthreads();
    }

    #pragma unroll
    for (int mt = 0; mt < 4; mt++) {
        #pragma unroll
        for (int nt = 0; nt < 4; nt++) {
            int coln = bn * 128 + wn * 32 + nt * 8 + 2 * t;
            #pragma unroll
            for (int half = 0; half < 2; half++) {
                int row = bm * 128 + wm * 64 + mt * 16 + g + half * 8;
                float v0 = acc[mt][nt][half * 2 + 0];
                float v1 = acc[mt][nt][half * 2 + 1];
                if (QKV) {
                    int b_ = row >> 10, i_ = row & 1023;
                    int tsel = coln >> 8, c_ = coln & 255;
                    int h = c_ >> 5, d = c_ & 31;
                    float* dst = (tsel == 0) ? g_q : (tsel == 1) ? g_k : g_v;
                    *(float2*)&dst[((size_t)(b_ * 8 + h) * 1024 + i_) * 32 + d] =
                        make_float2(v0, v1);
                } else {
                    if (row < M) {
                        *(float2*)&out[(size_t)row * 256 + coln] =
                            make_float2(v0 + bias[coln], v1 + bias[coln + 1]);
                    }
                }
            }
        }
    }
}

// ---------------- bilinear 7x7 -> 32x32 (jax half-pixel == clamped bilerp) ---
__device__ __forceinline__ float bilerp7(const float* __restrict__ t, int y, int x) {
    float sy = (y + 0.5f) * 0.21875f - 0.5f;
    float sx = (x + 0.5f) * 0.21875f - 0.5f;
    sy = fminf(fmaxf(sy, 0.f), 6.f);
    sx = fminf(fmaxf(sx, 0.f), 6.f);
    int y0 = (int)sy, x0 = (int)sx;
    int y1 = min(y0 + 1, 6), x1 = min(x0 + 1, 6);
    float fy = sy - (float)y0, fx = sx - (float)x0;
    float v00 = t[y0 * 7 + x0], v01 = t[y0 * 7 + x1];
    float v10 = t[y1 * 7 + x0], v11 = t[y1 * 7 + x1];
    return (1.f - fy) * ((1.f - fx) * v00 + fx * v01)
         + fy * ((1.f - fx) * v10 + fx * v11);
}

// ---------------- fused aux: pool | pb | ab in one launch ---------------------
#define AUX_RANGE 1568
__global__ void aux_kernel(const float* __restrict__ an,
                           const float* __restrict__ ahb,
                           const float* __restrict__ awb,
                           const float* __restrict__ na,
                           const float* __restrict__ hab,
                           const float* __restrict__ wab) {
    int blk = blockIdx.x;
    if (blk < AUX_RANGE) {
        int idx = blk * 256 + threadIdx.x;          // pool
        int c = idx & 255;
        int a = (idx >> 8) % 49;
        int b = idx / (49 * 256);
        int ay = a / 7, ax = a % 7;
        int h = c >> 5, d = c & 31;
        const float* base = g_q + (size_t)(b * 8 + h) * 1024 * 32 + d;
        int ys = c_starts[ay], ye = c_ends[ay];
        int xs = c_starts[ax], xe = c_ends[ax];
        float s = 0.f;
        for (int y = ys; y < ye; y++)
            for (int xx = xs; xx < xe; xx++)
                s += base[(y * 32 + xx) * 32];
        s /= (float)((ye - ys) * (xe - xs));
        g_ah[((size_t)(b * 8 + h) * 49 + a) * 32 + d] = s;
    } else if (blk < 2 * AUX_RANGE) {
        int idx = (blk - AUX_RANGE) * 256 + threadIdx.x;  // pb
        int x = idx & 31, y = (idx >> 5) & 31;
        int a = (idx >> 10) % 49, h = idx / (49 * 1024);
        float v = bilerp7(an + (h * 49 + a) * 49, y, x);
        v += ahb[(h * 49 + a) * 32 + y] + awb[(h * 49 + a) * 32 + x];
        g_pb[idx] = v;
    } else {
        int idx = (blk - 2 * AUX_RANGE) * 256 + threadIdx.x;  // ab (transposed)
        int i = idx & 1023;
        int a = (idx >> 10) % 49;
        int h = idx / (49 * 1024);
        float v = bilerp7(na + (h * 49 + a) * 49, i >> 5, i & 31);
        v += hab[(h * 32 + (i >> 5)) * 49 + a] + wab[(h * 32 + (i & 31)) * 49 + a];
        g_ab[idx] = v;
    }
}

// ---------------- TENSOR-CORE agent attention, token-split partials ----------
#define AA_SMEM_FLOATS (64*36 + 128*36 + 32*132 + 64*132 + 64)
__global__ __launch_bounds__(256) void agent_attn_tc() {
    extern __shared__ __align__(16) float smp[];
    float* ahs = smp;
    float* Kt  = ahs + 64 * 36;
    float* Vt  = Kt + 128 * 36;
    float* Ss  = Vt + 32 * 132;
    float* l_s = Ss + 64 * 132;

    const int tk = blockIdx.x;
    const int bh = blockIdx.y;
    const int tid = threadIdx.x;
    const int warp = tid >> 5, lane = tid & 31;
    const int g = lane >> 2, t = lane & 3;
    const int h = bh & 7;
    const int mt = warp >> 1;
    const int whalf = warp & 1;

    for (int j = tid; j < 64 * 32; j += 256) {
        int a = j >> 5, d = j & 31;
        float v = (a < 49) ? g_ah[(size_t)bh * 1568 + a * 32 + d] : 0.f;
        ahs[a * 36 + d] = tf32r(v);
    }
    if (tid < 64) l_s[tid] = 0.f;

    float pv[2][4] = {};
    __syncthreads();

    for (int it = tk * 4; it < tk * 4 + 4; it++) {
        const int i0 = it * 128;
        {
            const float4* src = (const float4*)(g_k + ((size_t)bh * 1024 + i0) * 32);
            for (int j = tid; j < 1024; j += 256) {
                float4 v = src[j];
                float* dst = &Kt[(j >> 3) * 36 + ((j & 7) << 2)];
                dst[0] = tf32r(v.x); dst[1] = tf32r(v.y);
                dst[2] = tf32r(v.z); dst[3] = tf32r(v.w);
            }
        }
        {
            const float4* src = (const float4*)(g_v + ((size_t)bh * 1024 + i0) * 32);
            for (int j = tid; j < 1024; j += 256) {
                float4 v = src[j];
                int tok = j >> 3, d4 = (j & 7) << 2;
                Vt[(d4 + 0) * 132 + tok] = tf32r(v.x);
                Vt[(d4 + 1) * 132 + tok] = tf32r(v.y);
                Vt[(d4 + 2) * 132 + tok] = tf32r(v.z);
                Vt[(d4 + 3) * 132 + tok] = tf32r(v.w);
            }
        }
        __syncthreads();

        {
            float c[8][4] = {};
            const uint32_t* A = (const uint32_t*)ahs;
            const uint32_t* B = (const uint32_t*)Kt;
            #pragma unroll
            for (int ks = 0; ks < 4; ks++) {
                const int kb = ks * 8;
                uint32_t af[4];
                af[0] = A[(mt * 16 + g) * 36 + kb + t];
                af[1] = A[(mt * 16 + g + 8) * 36 + kb + t];
                af[2] = A[(mt * 16 + g) * 36 + kb + t + 4];
                af[3] = A[(mt * 16 + g + 8) * 36 + kb + t + 4];
                #pragma unroll
                for (int nt = 0; nt < 8; nt++) {
                    int nr = whalf * 64 + nt * 8 + g;
                    uint32_t bf[2] = { B[nr * 36 + kb + t], B[nr * 36 + kb + t + 4] };
                    mma_tf32(c[nt], af, bf);
                }
            }
            const float* pbb = g_pb + (size_t)h * 49 * 1024 + i0;
            const int r0 = mt * 16 + g, r1 = r0 + 8;
            #pragma unroll
            for (int nt = 0; nt < 8; nt++) {
                int col = whalf * 64 + nt * 8 + 2 * t;
                float2 b0 = (r0 < 49) ? *(const float2*)&pbb[(size_t)r0 * 1024 + col]
                                      : make_float2(0.f, 0.f);
                float2 b1 = (r1 < 49) ? *(const float2*)&pbb[(size_t)r1 * 1024 + col]
                                      : make_float2(0.f, 0.f);
                *(float2*)&Ss[r0 * 132 + col] =
                    make_float2(fmaf(c[nt][0], SCALE, b0.x), fmaf(c[nt][1], SCALE, b0.y));
                *(float2*)&Ss[r1 * 132 + col] =
                    make_float2(fmaf(c[nt][2], SCALE, b1.x), fmaf(c[nt][3], SCALE, b1.y));
            }
        }
        __syncthreads();

        {
            int a = tid >> 2, q = tid & 3;
            float ts = 0.f;
            float4* row = (float4*)&Ss[a * 132 + q * 32];
            #pragma unroll
            for (int k2 = 0; k2 < 8; k2++) {
                float4 v = row[k2];
                v.x = tf32r(exp_fast(v.x)); v.y = tf32r(exp_fast(v.y));
                v.z = tf32r(exp_fast(v.z)); v.w = tf32r(exp_fast(v.w));
                row[k2] = v;
                ts += v.x + v.y + v.z + v.w;
            }
            ts += __shfl_xor_sync(0xffffffffu, ts, 1);
            ts += __shfl_xor_sync(0xffffffffu, ts, 2);
            if (q == 0) l_s[a] += ts;
        }
        __syncthreads();

        {
            const uint32_t* A = (const uint32_t*)Ss;
            const uint32_t* B = (const uint32_t*)Vt;
            #pragma unroll
            for (int ks = 0; ks < 16; ks++) {
                const int kb = ks * 8;
                uint32_t af[4];
                af[0] = A[(mt * 16 + g) * 132 + kb + t];
                af[1] = A[(mt * 16 + g + 8) * 132 + kb + t];
                af[2] = A[(mt * 16 + g) * 132 + kb + t + 4];
                af[3] = A[(mt * 16 + g + 8) * 132 + kb + t + 4];
                #pragma unroll
                for (int x = 0; x < 2; x++) {
                    int nr = (whalf * 2 + x) * 8 + g;
                    uint32_t bf[2] = { B[nr * 132 + kb + t], B[nr * 132 + kb + t + 4] };
                    mma_tf32(pv[x], af, bf);
                }
            }
        }
        __syncthreads();
    }

    {
        float* avp = g_avp[tk];
        const int r0 = mt * 16 + g, r1 = r0 + 8;
        #pragma unroll
        for (int x = 0; x < 2; x++) {
            int col = (whalf * 2 + x) * 8 + 2 * t;
            if (r0 < 49)
                *(float2*)&avp[(size_t)bh * 1568 + r0 * 32 + col] =
                    make_float2(pv[x][0], pv[x][1]);
            if (r1 < 49)
                *(float2*)&avp[(size_t)bh * 1568 + r1 * 32 + col] =
                    make_float2(pv[x][2], pv[x][3]);
        }
        if (tid < 49) g_lp[tk][(size_t)bh * 49 + tid] = l_s[tid];
    }
}

// ---------------- TENSOR-CORE q-attn + depthwise conv ------------------------
// grid (8, 256): itile = 128 tokens, bh; 256 thr / 8 warps, warp = 16 token rows
// S = Q@ah^T (mma, Q A-frags from gmem) + ab; exp; out = P@avT (lrec folded)
// smem: ahs 64*36 | avT 32*68 | Ss 128*68 | sum_s 128 | uni(absm 128*52 / vsm 6*VROW) | wsm 288 | bsm 32 | lrec 52
#define VROW (34 * 33)
#define A2_SMEM_FLOATS (64*36 + 32*68 + 128*68 + 128 + 6*VROW + 288 + 32 + 52)
__global__ __launch_bounds__(256) void attn2_tc(const float* __restrict__ dwc_w,
                                                const float* __restrict__ dwc_b) {
    extern __shared__ __align__(16) float smp[];
    float* ahs   = smp;
    float* avT   = ahs + 64 * 36;
    float* Ss    = avT + 32 * 68;
    float* sum_s = Ss + 128 * 68;
    float* uni   = sum_s + 128;          // absm then vsm
    float* wsm   = uni + 6 * VROW;
    float* bsm   = wsm + 288;
    float* lrec  = bsm + 32;

    const int itile = blockIdx.x, bh = blockIdx.y;
    const int tid = threadIdx.x;
    const int warp = tid >> 5, lane = tid & 31;
    const int g = lane >> 2, t = lane & 3;
    const int h = bh & 7, b_ = bh >> 3;
    const int i0 = itile * 128;
    const int y0 = itile * 4;

    // phase 0a: lrec
    if (tid < 49)
        lrec[tid] = 1.f / (g_lp[0][(size_t)bh * 49 + tid] + g_lp[1][(size_t)bh * 49 + tid]);
    if (tid < 32) bsm[tid] = dwc_b[h * 32 + tid];
    for (int j = tid; j < 288; j += 256) wsm[j] = dwc_w[(h * 32) * 9 + j];
    __syncthreads();

    // phase 0b: ahs (tf32, pad 0), avT[d][a] = (avp0+avp1)*lrec (tf32), absm staging
    const float* avp0 = g_avp[0] + (size_t)bh * 1568;
    const float* avp1 = g_avp[1] + (size_t)bh * 1568;
    for (int j = tid; j < 64 * 32; j += 256) {
        int a = j >> 5, d = j & 31;
        float av = 0.f, ahv = 0.f;
        if (a < 49) {
            ahv = g_ah[(size_t)bh * 1568 + j];
            av = (avp0[j] + avp1[j]) * lrec[a];
        }
        ahs[a * 36 + d] = tf32r(ahv);
        avT[d * 68 + a] = tf32r(av);
    }
    float* absm = uni;
    const float* abg = g_ab + (size_t)h * 49 * 1024 + i0;
    for (int j = tid; j < 49 * 128; j += 256) {
        int a = j >> 7, row = j & 127;
        absm[row * 52 + a] = abg[(size_t)a * 1024 + row];
    }
    __syncthreads();

    const int r0 = warp * 16 + g, r1 = r0 + 8;

    // phase 1: scores mma; A-fragments straight from gmem Q
    float rsum0 = 0.f, rsum1 = 0.f;
    {
        float c[8][4] = {};
        const float* Q = g_q + ((size_t)bh * 1024 + i0) * 32;
        const uint32_t* B = (const uint32_t*)ahs;
        #pragma unroll
        for (int ks = 0; ks < 4; ks++) {
            const int kb = ks * 8;
            uint32_t af[4];
            af[0] = f2tf32(Q[(size_t)r0 * 32 + kb + t]);
            af[1] = f2tf32(Q[(size_t)r1 * 32 + kb + t]);
            af[2] = f2tf32(Q[(size_t)r0 * 32 + kb + t + 4]);
            af[3] = f2tf32(Q[(size_t)r1 * 32 + kb + t + 4]);
            #pragma unroll
            for (int nt = 0; nt < 8; nt++) {
                int nr = nt * 8 + g;
                uint32_t bf[2] = { B[nr * 36 + kb + t], B[nr * 36 + kb + t + 4] };
                mma_tf32(c[nt], af, bf);
            }
        }
        // epilogue: exp(c*SCALE + ab), zero for cols >= 49, tf32-round, row sums
        #pragma unroll
        for (int nt = 0; nt < 8; nt++) {
            int col = nt * 8 + 2 * t;
            float s00 = 0.f, s01 = 0.f, s10 = 0.f, s11 = 0.f;
            if (col < 49) {
                s00 = tf32r(exp_fast(fmaf(c[nt][0], SCALE, absm[r0 * 52 + col])));
                s10 = tf32r(exp_fast(fmaf(c[nt][2], SCALE, absm[r1 * 52 + col])));
            }
            if (col + 1 < 49) {
                s01 = tf32r(exp_fast(fmaf(c[nt][1], SCALE, absm[r0 * 52 + col + 1])));
                s11 = tf32r(exp_fast(fmaf(c[nt][3], SCALE, absm[r1 * 52 + col + 1])));
            }
            *(float2*)&Ss[r0 * 68 + col] = make_float2(s00, s01);
            *(float2*)&Ss[r1 * 68 + col] = make_float2(s10, s11);
            rsum0 += s00 + s01;
            rsum1 += s10 + s11;
        }
        rsum0 += __shfl_xor_sync(0xffffffffu, rsum0, 1);
        rsum0 += __shfl_xor_sync(0xffffffffu, rsum0, 2);
        rsum1 += __shfl_xor_sync(0xffffffffu, rsum1, 1);
        rsum1 += __shfl_xor_sync(0xffffffffu, rsum1, 2);
        if (t == 0) { sum_s[r0] = rsum0; sum_s[r1] = rsum1; }
    }
    __syncthreads();

    // phase 2: out = P @ avT  (M=128 tok, N=32 d, K=64 agents)
    float c2[4][4] = {};
    {
        const uint32_t* A = (const uint32_t*)Ss;
        const uint32_t* B = (const uint32_t*)avT;
        #pragma unroll
        for (int ks = 0; ks < 8; ks++) {
            const int kb = ks * 8;
            uint32_t af[4];
            af[0] = A[r0 * 68 + kb + t];
            af[1] = A[r1 * 68 + kb + t];
            af[2] = A[r0 * 68 + kb + t + 4];
            af[3] = A[r1 * 68 + kb + t + 4];
            #pragma unroll
            for (int nt = 0; nt < 4; nt++) {
                int nr = nt * 8 + g;
                uint32_t bf[2] = { B[nr * 68 + kb + t], B[nr * 68 + kb + t + 4] };
                mma_tf32(c2[nt], af, bf);
            }
        }
    }
    __syncthreads();

    // phase 3: v halo into uni (overwrites absm)
    float* vsm = uni;
    for (int j = tid; j < 6 * VROW; j += 256) vsm[j] = 0.f;
    __syncthreads();
    for (int j = tid; j < 6 * 1024; j += 256) {
        int row = j >> 10;
        int rem = j & 1023;
        int x = rem >> 5, d = rem & 31;
        int gy = y0 - 1 + row;
        if (gy >= 0 && gy < 32)
            vsm[row * VROW + (x + 1) * 33 + d] =
                g_v[((size_t)bh * 1024 + gy * 32 + x) * 32 + d];
    }
    __syncthreads();

    // phase 4: dwc + writeback
    {
        const float inv0 = 1.f / sum_s[r0];
        const float inv1 = 1.f / sum_s[r1];
        const float* vb0 = vsm + (r0 >> 5) * VROW + (r0 & 31) * 33;
        const float* vb1 = vsm + (r1 >> 5) * VROW + (r1 & 31) * 33;
        float* dst0 = g_attn + ((size_t)(b_ * 1024 + i0 + r0) * 256) + h * 32;
        float* dst1 = g_attn + ((size_t)(b_ * 1024 + i0 + r1) * 256) + h * 32;
        #pragma unroll
        for (int nt = 0; nt < 4; nt++) {
            int col = nt * 8 + 2 * t;
            float o[4];
            #pragma unroll
            for (int half = 0; half < 2; half++) {
                int cc = col + half;
                const float* wk = wsm + cc * 9;
                float d0 = bsm[cc], d1 = bsm[cc];
                #pragma unroll
                for (int dy = 0; dy < 3; dy++) {
                    const float* p0 = vb0 + dy * VROW + cc;
                    const float* p1 = vb1 + dy * VROW + cc;
                    d0 += p0[0] * wk[dy*3] + p0[33] * wk[dy*3+1] + p0[66] * wk[dy*3+2];
                    d1 += p1[0] * wk[dy*3] + p1[33] * wk[dy*3+1] + p1[66] * wk[dy*3+2];
                }
                o[half]     = fmaf(c2[nt][half],     inv0, d0);
                o[2 + half] = fmaf(c2[nt][2 + half], inv1, d1);
            }
            *(float2*)&dst0[col] = make_float2(o[0], o[1]);
            *(float2*)&dst1[col] = make_float2(o[2], o[3]);
        }
    }
}

// ---------------- launch ------------------------------------------------------
// ORDER NOTE: launch #4 = attn2_tc (verify tensor-core port).
extern "C" void kernel_launch(void* const* d_in, const int* in_sizes, int n_in,
                              void* d_out, int out_size) {
    const float* x      = (const float*)d_in[0];
    const float* qkv_w  = (const float*)d_in[1];
    const float* proj_w = (const float*)d_in[2];
    const float* proj_b = (const float*)d_in[3];
    const float* dwc_w  = (const float*)d_in[4];
    const float* dwc_b  = (const float*)d_in[5];
    const float* an_b   = (const float*)d_in[6];
    const float* ah_b   = (const float*)d_in[7];
    const float* aw_b   = (const float*)d_in[8];
    const float* na_b   = (const float*)d_in[9];
    const float* ha_b   = (const float*)d_in[10];
    const float* wa_b   = (const float*)d_in[11];
    float* out = (float*)d_out;

    const int a2_smem = A2_SMEM_FLOATS * 4;
    cudaFuncSetAttribute(attn2_tc,
                         cudaFuncAttributeMaxDynamicSharedMemorySize, a2_smem);
    const int aa_smem = AA_SMEM_FLOATS * 4;
    cudaFuncSetAttribute(agent_attn_tc,
                         cudaFuncAttributeMaxDynamicSharedMemorySize, aa_smem);

    gemm_tc<true><<<dim3(6, 256), 256>>>(x, qkv_w, nullptr, nullptr);            // 1
    aux_kernel<<<3 * AUX_RANGE, 256>>>(an_b, ah_b, aw_b, na_b, ha_b, wa_b);      // 2
    agent_attn_tc<<<dim3(2, BATCH * HEADS), 256, aa_smem>>>();                   // 3
    attn2_tc<<<dim3(8, BATCH * HEADS), 256, a2_smem>>>(dwc_w, dwc_b);            // 4 <- profiled
    gemm_tc<false><<<dim3(2, 257), 256>>>(x, proj_w, proj_b, out);               // 5
}